// round 6
// baseline (speedup 1.0000x reference)
#include <cuda_runtime.h>
#include <cstdint>

#define NUM_E   1024
#define DIM     128
#define HW      4096
#define NBLOCKS 512           // 65536 rows / 128 per CTA

// Output layout (flattened tuple, float32)
#define OFF_LOSS   8388608
#define OFF_IDX    8388609
#define OFF_COMMIT 8454145
#define OFF_CODE   8454146

__device__ float    d_enorm[NUM_E];
__device__ float    d_blockS[NBLOCKS];
__device__ uint32_t d_ehi[NUM_E * DIM];   // tf32 bits of e
__device__ uint32_t d_elo[NUM_E * DIM];   // tf32 bits of (e - hi)

// SMEM (byte offsets)
//  A_hi frag-layout [16 k_step][8 m_blk] x 512B      @0       64KB
//  A_lo                                              @65536   64KB
//  B buffer  hi 16KB + lo 16KB (frag layout)         @131072  32KB
//    (prologue z-stage 32x132 f32 and final cand[16][128] u64 alias here)
//  e2sm [1024 f32]                                   @163840  4KB
//  z2sm [128 f32]                                    @167936
//  idxsm[128 i32]                                    @168448
//  wsum [8 f32]                                      @168960
#define SM_AHI  0
#define SM_ALO  65536
#define SM_B    131072
#define SM_E2   163840
#define SM_Z2   167936
#define SM_IDX  168448
#define SM_WSUM 168960
#define SMEM_BYTES 169024

static __device__ __forceinline__ uint32_t cvt_tf32(float x) {
    uint32_t b;
    asm("cvt.rna.tf32.f32 %0, %1;" : "=r"(b) : "f"(x));
    return b;
}
static __device__ __forceinline__ void mma8(float c[4], const uint32_t a[4],
                                            uint32_t b0, uint32_t b1) {
    asm("mma.sync.aligned.m16n8k8.row.col.f32.tf32.tf32.f32 "
        "{%0,%1,%2,%3}, {%4,%5,%6,%7}, {%8,%9}, {%0,%1,%2,%3};"
        : "+f"(c[0]), "+f"(c[1]), "+f"(c[2]), "+f"(c[3])
        : "r"(a[0]), "r"(a[1]), "r"(a[2]), "r"(a[3]), "r"(b0), "r"(b1));
}
// element (m 0..127, k 0..127) -> byte offset in A frag layout
static __device__ __forceinline__ int afrag_off(int m, int k) {
    int lane = ((m & 7) << 2) | (k & 3);
    int slot = ((m >> 3) & 1) | (((k >> 2) & 1) << 1);
    return ((((k >> 3) << 3) + (m >> 4)) << 9) + (lane << 4) + (slot << 2);
}
// element (n 0..127 within tile, k 0..31 within chunk) -> offset in B frag layout
static __device__ __forceinline__ int bfrag_off(int n, int k) {
    int nn = n & 15, npair = n >> 4;
    int lane = ((nn & 7) << 2) | (k & 3);
    int slot = ((k >> 2) & 1) | ((nn >> 3) << 1);
    return ((((k >> 3) << 3) + npair) << 9) + (lane << 4) + (slot << 2);
}

// ---------------------------------------------------------------------------
__global__ void enorm_kernel(const float* __restrict__ emb) {
    int k    = blockIdx.x * 8 + (threadIdx.x >> 5);
    int lane = threadIdx.x & 31;
    const float4* row = (const float4*)(emb + (size_t)k * DIM);
    float4 v = row[lane];
    float s = __fadd_rn(__fadd_rn(__fmul_rn(v.x, v.x), __fmul_rn(v.y, v.y)),
                        __fadd_rn(__fmul_rn(v.z, v.z), __fmul_rn(v.w, v.w)));
    #pragma unroll
    for (int o = 16; o; o >>= 1) s = __fadd_rn(s, __shfl_xor_sync(0xffffffffu, s, o));
    if (lane == 0) d_enorm[k] = s;
}

__global__ void prep_split_kernel(const float* __restrict__ emb) {
    int i = blockIdx.x * 256 + threadIdx.x;        // 512x256 covers 131072
    float v = emb[i];
    uint32_t hb = cvt_tf32(v);
    d_ehi[i] = hb;
    d_elo[i] = cvt_tf32(v - __uint_as_float(hb));
}

// ---------------------------------------------------------------------------
// Main: 512 CTAs x 256 threads. Warp (wid): warp_m=wid&1 (M 64), warp_n=wid>>1
// (N 32). Per warp: 4 m-frags x 4 n-frags of m16n8k8.
// ---------------------------------------------------------------------------
__global__ __launch_bounds__(256, 1)
void vq_main_kernel(const float* __restrict__ z,
                    const float* __restrict__ emb,
                    float* __restrict__ out) {
    extern __shared__ char smem[];
    float* e2sm = (float*)(smem + SM_E2);
    float* z2sm = (float*)(smem + SM_Z2);
    int*   idxsm = (int*)(smem + SM_IDX);
    float* wsum = (float*)(smem + SM_WSUM);

    const int t    = threadIdx.x;
    const int wid  = t >> 5;
    const int lane = t & 31;
    const int warp_m = wid & 1;
    const int warp_n = wid >> 1;
    const int blk = blockIdx.x;
    const int n0  = blk * 128;
    const int b   = n0 >> 12;
    const int hw0 = n0 & 4095;
    const float* zbase = z + (size_t)b * (DIM * HW) + hw0;

    // e2 table
    #pragma unroll
    for (int i = 0; i < 4; i++) e2sm[i * 256 + t] = d_enorm[i * 256 + t];

    // ---- prologue: A hi/lo frag layout + strictly sequential z2 per row ----
    float* zst = (float*)(smem + SM_B);            // 32 x 132 stage
    float z2 = 0.f;
    for (int c4 = 0; c4 < 4; c4++) {
        __syncthreads();
        #pragma unroll
        for (int i = 0; i < 4; i++) {
            int id = t + 256 * i;                  // 1024 float4 = 32d x 128n
            int dl = id >> 5, hw4 = (id & 31) * 4;
            float4 v = *(const float4*)(zbase + (size_t)(c4 * 32 + dl) * HW + hw4);
            *(float4*)(&zst[dl * 132 + hw4]) = v;
        }
        __syncthreads();
        if (t < 128) {
            #pragma unroll 1
            for (int j = 0; j < 32; j++) {         // d ascending: sequential z2
                float v = zst[j * 132 + t];
                z2 = __fadd_rn(z2, __fmul_rn(v, v));
                uint32_t hb = cvt_tf32(v);
                uint32_t lb = cvt_tf32(v - __uint_as_float(hb));
                int off = afrag_off(t, c4 * 32 + j);
                *(uint32_t*)(smem + SM_AHI + off) = hb;
                *(uint32_t*)(smem + SM_ALO + off) = lb;
            }
        }
    }
    if (t < 128) z2sm[t] = z2;
    __syncthreads();

    float z2r[8];
    #pragma unroll
    for (int mf = 0; mf < 4; mf++)
        #pragma unroll
        for (int h = 0; h < 2; h++)
            z2r[mf * 2 + h] = z2sm[warp_m * 64 + mf * 16 + h * 8 + (lane >> 2)];

    unsigned long long best[8];
    #pragma unroll
    for (int i = 0; i < 8; i++) best[i] = ~0ull;

    // B producer-side constants
    const int  code_loc = t >> 1;                  // 0..127 within n-tile
    const int  dh = (t & 1) << 4;                  // d-half within 32-chunk
    uint4 bh[4], bl[4];

    #pragma unroll 1
    for (int j = 0; j < 8; j++) {                  // n-tiles of 128 codes
        float acc[4][4][4];
        #pragma unroll
        for (int mf = 0; mf < 4; mf++)
            #pragma unroll
            for (int nf = 0; nf < 4; nf++)
                #pragma unroll
                for (int q = 0; q < 4; q++) acc[mf][nf][q] = 0.f;

        // prefetch chunk 0
        {
            const uint32_t* sh = d_ehi + (size_t)(j * 128 + code_loc) * DIM + dh;
            const uint32_t* sl = d_elo + (size_t)(j * 128 + code_loc) * DIM + dh;
            #pragma unroll
            for (int i = 0; i < 4; i++) {
                bh[i] = ((const uint4*)sh)[i];
                bl[i] = ((const uint4*)sl)[i];
            }
        }

        #pragma unroll
        for (int c = 0; c < 4; c++) {              // k-chunks of 32
            __syncthreads();                        // prev mma done reading B
            // STS chunk c (frag layout)
            #pragma unroll
            for (int i = 0; i < 4; i++) {
                uint32_t hv[4] = {bh[i].x, bh[i].y, bh[i].z, bh[i].w};
                uint32_t lv[4] = {bl[i].x, bl[i].y, bl[i].z, bl[i].w};
                #pragma unroll
                for (int e = 0; e < 4; e++) {
                    int off = bfrag_off(code_loc, dh + i * 4 + e);
                    *(uint32_t*)(smem + SM_B + off)         = hv[e];
                    *(uint32_t*)(smem + SM_B + 16384 + off) = lv[e];
                }
            }
            __syncthreads();
            // prefetch chunk c+1 (overlaps mma below)
            if (c < 3) {
                const uint32_t* sh = d_ehi + (size_t)(j * 128 + code_loc) * DIM
                                   + (c + 1) * 32 + dh;
                const uint32_t* sl = d_elo + (size_t)(j * 128 + code_loc) * DIM
                                   + (c + 1) * 32 + dh;
                #pragma unroll
                for (int i = 0; i < 4; i++) {
                    bh[i] = ((const uint4*)sh)[i];
                    bl[i] = ((const uint4*)sl)[i];
                }
            }
            // mma: 3 passes (Ahi*Bhi, Ahi*Blo, Alo*Bhi)
            #pragma unroll
            for (int pass = 0; pass < 3; pass++) {
                const int abase = (pass == 2) ? SM_ALO : SM_AHI;
                const int bbase = SM_B + ((pass == 1) ? 16384 : 0);
                #pragma unroll
                for (int ks = 0; ks < 4; ks++) {
                    int kg = c * 4 + ks;
                    uint4 af[4];
                    #pragma unroll
                    for (int mf = 0; mf < 4; mf++)
                        af[mf] = *(const uint4*)(smem + abase
                               + (((kg << 3) + (warp_m << 2) + mf) << 9) + (lane << 4));
                    uint4 bv0 = *(const uint4*)(smem + bbase
                               + (((ks << 3) + (warp_n << 1) + 0) << 9) + (lane << 4));
                    uint4 bv1 = *(const uint4*)(smem + bbase
                               + (((ks << 3) + (warp_n << 1) + 1) << 9) + (lane << 4));
                    uint32_t bfr[4][2] = {{bv0.x, bv0.y}, {bv0.z, bv0.w},
                                          {bv1.x, bv1.y}, {bv1.z, bv1.w}};
                    #pragma unroll
                    for (int mf = 0; mf < 4; mf++)
                        #pragma unroll
                        for (int nf = 0; nf < 4; nf++)
                            mma8(acc[mf][nf], (const uint32_t*)&af[mf],
                                 bfr[nf][0], bfr[nf][1]);
                }
            }
        }

        // scoring: s = fl(fl(z2+e2) - fl(2*dot)); packed (score,idx) running min
        float e2v[4][2];
        int   ncb[4];
        #pragma unroll
        for (int nf = 0; nf < 4; nf++) {
            ncb[nf] = j * 128 + warp_n * 32 + nf * 8 + ((lane & 3) << 1);
            e2v[nf][0] = e2sm[ncb[nf]];
            e2v[nf][1] = e2sm[ncb[nf] + 1];
        }
        #pragma unroll
        for (int mf = 0; mf < 4; mf++)
            #pragma unroll
            for (int nf = 0; nf < 4; nf++)
                #pragma unroll
                for (int h = 0; h < 2; h++)
                    #pragma unroll
                    for (int q = 0; q < 2; q++) {
                        float dot = acc[mf][nf][h * 2 + q];
                        float s = __fadd_rn(__fadd_rn(z2r[mf * 2 + h], e2v[nf][q]),
                                            __fmul_rn(-2.0f, dot));
                        unsigned long long u =
                            ((unsigned long long)__float_as_uint(s) << 32)
                            | (unsigned)(ncb[nf] + q);
                        if (u < best[mf * 2 + h]) best[mf * 2 + h] = u;
                    }
    }

    // ---- candidate dump (cand[ci][m] u64, aliases B) + reduce ----
    __syncthreads();
    unsigned long long* cand = (unsigned long long*)(smem + SM_B);
    {
        int ci = warp_n * 4 + (lane & 3);
        #pragma unroll
        for (int mf = 0; mf < 4; mf++)
            #pragma unroll
            for (int h = 0; h < 2; h++) {
                int m = warp_m * 64 + mf * 16 + h * 8 + (lane >> 2);
                cand[ci * 128 + m] = best[mf * 2 + h];
            }
    }
    __syncthreads();
    if (t < 128) {
        unsigned long long bv = cand[t];
        #pragma unroll
        for (int ci = 1; ci < 16; ci++) {
            unsigned long long u = cand[ci * 128 + t];
            if (u < bv) bv = u;
        }
        int idx = (int)(bv & 0xffffffffu);
        idxsm[t] = idx;
        out[OFF_IDX + n0 + t] = (float)idx;
    }
    __syncthreads();

    // ---- epilogue: z_q gather+write, loss partial (z re-read from global) ----
    float sloc = 0.f;
    #pragma unroll 4
    for (int r = 0; r < 64; r++) {
        int linear = t + (r << 8);
        int d = linear >> 7;
        int n = linear & 127;
        float v  = emb[(size_t)idxsm[n] * DIM + d];
        float zv = zbase[(size_t)d * HW + n];
        float diff = v - zv;
        sloc = fmaf(diff, diff, sloc);
        out[(size_t)b * (DIM * HW) + (size_t)d * HW + hw0 + n] = v;
    }
    #pragma unroll
    for (int o = 16; o; o >>= 1) sloc += __shfl_xor_sync(0xffffffffu, sloc, o);
    if (lane == 0) wsum[wid] = sloc;
    __syncthreads();
    if (t == 0) {
        float s = 0.f;
        #pragma unroll
        for (int i = 0; i < 8; i++) s += wsum[i];
        d_blockS[blk] = s;
    }
}

// ---------------------------------------------------------------------------
__global__ void finalize_kernel(float* __restrict__ out) {
    __shared__ float sh[NBLOCKS];
    int t = threadIdx.x;
    sh[t] = d_blockS[t];
    __syncthreads();
    for (int s = NBLOCKS / 2; s > 0; s >>= 1) {
        if (t < s) sh[t] += sh[t + s];
        __syncthreads();
    }
    if (t == 0) {
        float S = sh[0];
        out[OFF_LOSS]   = 1.25f * S;
        out[OFF_COMMIT] = 0.25f * S;
        out[OFF_CODE]   = S;
    }
}

// ---------------------------------------------------------------------------
extern "C" void kernel_launch(void* const* d_in, const int* in_sizes, int n_in,
                              void* d_out, int out_size) {
    const float* z   = (const float*)d_in[0];   // (16, 128, 64, 64)
    const float* emb = (const float*)d_in[1];   // (1024, 128)
    float* out = (float*)d_out;

    cudaFuncSetAttribute(vq_main_kernel,
                         cudaFuncAttributeMaxDynamicSharedMemorySize, SMEM_BYTES);

    enorm_kernel<<<128, 256>>>(emb);
    prep_split_kernel<<<512, 256>>>(emb);
    vq_main_kernel<<<NBLOCKS, 256, SMEM_BYTES>>>(z, emb, out);
    finalize_kernel<<<1, NBLOCKS>>>(out);
}

// round 7
// speedup vs baseline: 1.5853x; 1.5853x over previous
#include <cuda_runtime.h>
#include <cstdint>

#define NUM_E   1024
#define DIM     128
#define HW      4096
#define NBLOCKS 512           // 65536 rows / 128 per CTA

// Output layout (flattened tuple, float32)
#define OFF_LOSS   8388608
#define OFF_IDX    8388609
#define OFF_COMMIT 8454145
#define OFF_CODE   8454146

#define MARGIN 1.2e-4f

__device__ float    d_enorm[NUM_E];
__device__ float    d_blockS[NBLOCKS];
__device__ uint32_t d_ehi[NUM_E * DIM];   // tf32 bits of e
__device__ unsigned d_ctr = 0;

// SMEM (byte offsets)
#define SM_AHI  0          // A-hi frag layout, 64KB
#define SM_Z    65536      // z plain [d][n] f32, 64KB
#define SM_B    131072     // B chunk double buffer 2 x 16KB
#define SM_E2   163840     // 1024 f32
#define SM_Z2   167936     // 128 f32
#define SM_CAND 168448     // 128 rows x 32 u64 = 32KB
#define SM_IDX  201216     // 128 i32
#define SM_WSUM 201728     // 8 f32
#define SM_FLAG 201760
#define SMEM_BYTES 201792

static __device__ __forceinline__ uint32_t cvt_tf32(float x) {
    uint32_t b;
    asm("cvt.rna.tf32.f32 %0, %1;" : "=r"(b) : "f"(x));
    return b;
}
static __device__ __forceinline__ void mma8(float c[4], const uint32_t a[4],
                                            uint32_t b0, uint32_t b1) {
    asm("mma.sync.aligned.m16n8k8.row.col.f32.tf32.tf32.f32 "
        "{%0,%1,%2,%3}, {%4,%5,%6,%7}, {%8,%9}, {%0,%1,%2,%3};"
        : "+f"(c[0]), "+f"(c[1]), "+f"(c[2]), "+f"(c[3])
        : "r"(a[0]), "r"(a[1]), "r"(a[2]), "r"(a[3]), "r"(b0), "r"(b1));
}
// element (m 0..127, k 0..127) -> byte offset in A frag layout
static __device__ __forceinline__ int afrag_off(int m, int k) {
    int lane = ((m & 7) << 2) | (k & 3);
    int slot = ((m >> 3) & 1) | (((k >> 2) & 1) << 1);
    return ((((k >> 3) << 3) + (m >> 4)) << 9) + (lane << 4) + (slot << 2);
}
// element (n 0..127 in tile, k 0..31 in chunk) -> offset in B frag layout
static __device__ __forceinline__ int bfrag_off(int n, int k) {
    int nn = n & 15, npair = n >> 4;
    int lane = ((nn & 7) << 2) | (k & 3);
    int slot = ((k >> 2) & 1) | ((nn >> 3) << 1);
    return ((((k >> 3) << 3) + npair) << 9) + (lane << 4) + (slot << 2);
}

// ---------------------------------------------------------------------------
// Prep: per-code ||e||^2 + tf32-hi split. 128 blocks x 256, one warp per code.
// ---------------------------------------------------------------------------
__global__ void prep_kernel(const float* __restrict__ emb) {
    int k    = blockIdx.x * 8 + (threadIdx.x >> 5);
    int lane = threadIdx.x & 31;
    const float4* row = (const float4*)(emb + (size_t)k * DIM);
    float4 v = row[lane];
    float s = __fadd_rn(__fadd_rn(__fmul_rn(v.x, v.x), __fmul_rn(v.y, v.y)),
                        __fadd_rn(__fmul_rn(v.z, v.z), __fmul_rn(v.w, v.w)));
    #pragma unroll
    for (int o = 16; o; o >>= 1) s = __fadd_rn(s, __shfl_xor_sync(0xffffffffu, s, o));
    if (lane == 0) d_enorm[k] = s;
    uint4 hb;
    hb.x = cvt_tf32(v.x); hb.y = cvt_tf32(v.y);
    hb.z = cvt_tf32(v.z); hb.w = cvt_tf32(v.w);
    ((uint4*)(d_ehi + (size_t)k * DIM))[lane] = hb;
}

// ---------------------------------------------------------------------------
// Main: 512 CTAs x 256 threads. warp_m=wid&1 (M64), warp_n=wid>>1 (N32).
// ---------------------------------------------------------------------------
__global__ __launch_bounds__(256, 1)
void vq_main_kernel(const float* __restrict__ z,
                    const float* __restrict__ emb,
                    float* __restrict__ out) {
    extern __shared__ char smem[];
    float* zpl  = (float*)(smem + SM_Z);      // zpl[d*128+n]
    float* e2sm = (float*)(smem + SM_E2);
    float* z2sm = (float*)(smem + SM_Z2);
    int*   idxsm = (int*)(smem + SM_IDX);
    float* wsum  = (float*)(smem + SM_WSUM);
    unsigned long long* cand = (unsigned long long*)(smem + SM_CAND);

    const int t    = threadIdx.x;
    const int wid  = t >> 5;
    const int lane = t & 31;
    const int warp_m = wid & 1;
    const int warp_n = wid >> 1;
    const int blk = blockIdx.x;
    const int n0  = blk * 128;
    const int b   = n0 >> 12;
    const int hw0 = n0 & 4095;
    const float* zbase = z + (size_t)b * (DIM * HW) + hw0;

    // e2 table
    #pragma unroll
    for (int i = 0; i < 4; i++) e2sm[i * 256 + t] = d_enorm[i * 256 + t];

    // ---- load z tile into zpl[d][n] (coalesced float4) ----
    #pragma unroll
    for (int i = 0; i < 16; i++) {
        int id = t + 256 * i;                  // 4096 float4
        int dl = id >> 5, hw4 = (id & 31) * 4;
        float4 v = *(const float4*)(zbase + (size_t)dl * HW + hw4);
        *(float4*)(&zpl[dl * 128 + hw4]) = v;
    }
    __syncthreads();

    // ---- A-hi frags + strictly sequential z2 per row ----
    if (t < 128) {
        float z2 = 0.f;
        #pragma unroll 4
        for (int d = 0; d < 128; d++) {        // d ascending: sequential z2
            float v = zpl[d * 128 + t];
            z2 = __fadd_rn(z2, __fmul_rn(v, v));
            *(uint32_t*)(smem + SM_AHI + afrag_off(t, d)) = cvt_tf32(v);
        }
        z2sm[t] = z2;
    }
    __syncthreads();

    float z2r[8];
    #pragma unroll
    for (int mf = 0; mf < 4; mf++)
        #pragma unroll
        for (int h = 0; h < 2; h++)
            z2r[mf * 2 + h] = z2sm[warp_m * 64 + mf * 16 + h * 8 + (lane >> 2)];

    unsigned long long best0[8], best1[8];
    #pragma unroll
    for (int i = 0; i < 8; i++) { best0[i] = ~0ull; best1[i] = ~0ull; }

    const int code_loc = t >> 1;               // 0..127 within n-tile
    const int dh = (t & 1) << 4;               // d-half of 32-chunk
    uint4 bh[4];

    #pragma unroll 1
    for (int j = 0; j < 8; j++) {              // n-tiles of 128 codes
        float acc[4][4][4];
        #pragma unroll
        for (int mf = 0; mf < 4; mf++)
            #pragma unroll
            for (int nf = 0; nf < 4; nf++)
                #pragma unroll
                for (int q = 0; q < 4; q++) acc[mf][nf][q] = 0.f;

        // prefetch chunk 0
        {
            const uint4* sh = (const uint4*)(d_ehi
                            + (size_t)(j * 128 + code_loc) * DIM + dh);
            #pragma unroll
            for (int i = 0; i < 4; i++) bh[i] = sh[i];
        }

        #pragma unroll
        for (int c = 0; c < 4; c++) {          // k-chunks of 32, dbl-buffered
            const int bbase = SM_B + (c & 1) * 16384;
            #pragma unroll
            for (int i = 0; i < 4; i++) {
                uint32_t hv[4] = {bh[i].x, bh[i].y, bh[i].z, bh[i].w};
                #pragma unroll
                for (int e = 0; e < 4; e++)
                    *(uint32_t*)(smem + bbase + bfrag_off(code_loc, dh + i * 4 + e)) = hv[e];
            }
            if (c < 3) {                       // prefetch next chunk
                const uint4* sh = (const uint4*)(d_ehi
                                + (size_t)(j * 128 + code_loc) * DIM + (c + 1) * 32 + dh);
                #pragma unroll
                for (int i = 0; i < 4; i++) bh[i] = sh[i];
            }
            __syncthreads();
            #pragma unroll
            for (int ks = 0; ks < 4; ks++) {
                int kg = c * 4 + ks;
                uint4 af[4];
                #pragma unroll
                for (int mf = 0; mf < 4; mf++)
                    af[mf] = *(const uint4*)(smem + SM_AHI
                           + (((kg << 3) + (warp_m << 2) + mf) << 9) + (lane << 4));
                uint4 bv0 = *(const uint4*)(smem + bbase
                           + (((ks << 3) + (warp_n << 1) + 0) << 9) + (lane << 4));
                uint4 bv1 = *(const uint4*)(smem + bbase
                           + (((ks << 3) + (warp_n << 1) + 1) << 9) + (lane << 4));
                uint32_t bfr[4][2] = {{bv0.x, bv0.y}, {bv0.z, bv0.w},
                                      {bv1.x, bv1.y}, {bv1.z, bv1.w}};
                #pragma unroll
                for (int mf = 0; mf < 4; mf++)
                    #pragma unroll
                    for (int nf = 0; nf < 4; nf++)
                        mma8(acc[mf][nf], (const uint32_t*)&af[mf],
                             bfr[nf][0], bfr[nf][1]);
            }
        }

        // approx scoring + per-slot top-2
        float e2v[4][2];
        int   ncb[4];
        #pragma unroll
        for (int nf = 0; nf < 4; nf++) {
            ncb[nf] = j * 128 + warp_n * 32 + nf * 8 + ((lane & 3) << 1);
            e2v[nf][0] = e2sm[ncb[nf]];
            e2v[nf][1] = e2sm[ncb[nf] + 1];
        }
        #pragma unroll
        for (int mf = 0; mf < 4; mf++)
            #pragma unroll
            for (int nf = 0; nf < 4; nf++)
                #pragma unroll
                for (int h = 0; h < 2; h++)
                    #pragma unroll
                    for (int q = 0; q < 2; q++) {
                        float dot = acc[mf][nf][h * 2 + q];
                        float s = __fadd_rn(__fadd_rn(z2r[mf * 2 + h], e2v[nf][q]),
                                            __fmul_rn(-2.0f, dot));
                        unsigned long long u =
                            ((unsigned long long)__float_as_uint(s) << 32)
                            | (unsigned)(ncb[nf] + q);
                        int sl = mf * 2 + h;
                        if (u < best0[sl]) { best1[sl] = best0[sl]; best0[sl] = u; }
                        else if (u < best1[sl]) { best1[sl] = u; }
                    }
    }

    // ---- dump candidates: cand[m][32] ----
    __syncthreads();
    {
        int ci = warp_n * 4 + (lane & 3);
        #pragma unroll
        for (int mf = 0; mf < 4; mf++)
            #pragma unroll
            for (int h = 0; h < 2; h++) {
                int m = warp_m * 64 + mf * 16 + h * 8 + (lane >> 2);
                cand[m * 32 + ci * 2 + 0] = best0[mf * 2 + h];
                cand[m * 32 + ci * 2 + 1] = best1[mf * 2 + h];
            }
    }
    __syncthreads();

    // ---- per-row: merge, margin-select, EXACT refine ----
    if (t < 128) {
        unsigned long long m0 = ~0ull;
        #pragma unroll
        for (int ci = 0; ci < 32; ci++) {
            unsigned long long u = cand[t * 32 + ci];
            if (u < m0) m0 = u;
        }
        float thr = __uint_as_float((uint32_t)(m0 >> 32)) + MARGIN;
        int cl[6]; int nc = 0;
        #pragma unroll
        for (int ci = 0; ci < 32; ci++) {
            unsigned long long u = cand[t * 32 + ci];
            float sv = __uint_as_float((uint32_t)(u >> 32));
            if (sv <= thr && nc < 6) cl[nc++] = (int)(u & 0xffffffffu);
        }
        float z2 = z2sm[t];
        unsigned long long bestu = ~0ull;
        for (int i = 0; i < nc; i++) {
            int k = cl[i];
            const float4* er = (const float4*)(emb + (size_t)k * DIM);
            float a0 = 0.f, a1 = 0.f, a2 = 0.f, a3 = 0.f;
            #pragma unroll 8
            for (int q = 0; q < 32; q++) {
                float4 e4 = er[q];
                int d0 = q * 4;
                a0 = fmaf(zpl[(d0 + 0) * 128 + t], e4.x, a0);
                a1 = fmaf(zpl[(d0 + 1) * 128 + t], e4.y, a1);
                a2 = fmaf(zpl[(d0 + 2) * 128 + t], e4.z, a2);
                a3 = fmaf(zpl[(d0 + 3) * 128 + t], e4.w, a3);
            }
            float dot = __fadd_rn(__fadd_rn(a0, a1), __fadd_rn(a2, a3));
            float s = __fadd_rn(__fadd_rn(z2, e2sm[k]), __fmul_rn(-2.0f, dot));
            unsigned long long u =
                ((unsigned long long)__float_as_uint(s) << 32) | (unsigned)k;
            if (u < bestu) bestu = u;
        }
        int idx = (int)(bestu & 0xffffffffu);
        idxsm[t] = idx;
        out[OFF_IDX + n0 + t] = (float)idx;
    }
    __syncthreads();

    // ---- epilogue: z_q gather+write, loss partial ----
    float sloc = 0.f;
    #pragma unroll 4
    for (int r = 0; r < 64; r++) {
        int linear = t + (r << 8);
        int d = linear >> 7;
        int n = linear & 127;
        float v  = emb[(size_t)idxsm[n] * DIM + d];
        float zv = zpl[d * 128 + n];
        float diff = v - zv;
        sloc = fmaf(diff, diff, sloc);
        out[(size_t)b * (DIM * HW) + (size_t)d * HW + hw0 + n] = v;
    }
    #pragma unroll
    for (int o = 16; o; o >>= 1) sloc += __shfl_xor_sync(0xffffffffu, sloc, o);
    if (lane == 0) wsum[wid] = sloc;
    __syncthreads();
    if (t == 0) {
        float s = 0.f;
        #pragma unroll
        for (int i = 0; i < 8; i++) s += wsum[i];
        d_blockS[blk] = s;
        __threadfence();
        unsigned v = atomicAdd(&d_ctr, 1u);
        *(unsigned*)(smem + SM_FLAG) = (v == (unsigned)(gridDim.x - 1));
    }
    __syncthreads();

    // ---- last block: deterministic finalize ----
    if (*(unsigned*)(smem + SM_FLAG)) {
        float* scratch = (float*)(smem + SM_CAND);
        scratch[t] = d_blockS[t] + d_blockS[t + 256];
        __syncthreads();
        for (int s = 128; s > 0; s >>= 1) {
            if (t < s) scratch[t] += scratch[t + s];
            __syncthreads();
        }
        if (t == 0) {
            float S = scratch[0];
            out[OFF_LOSS]   = 1.25f * S;
            out[OFF_COMMIT] = 0.25f * S;
            out[OFF_CODE]   = S;
            d_ctr = 0;                          // reset for next graph replay
        }
    }
}

// ---------------------------------------------------------------------------
extern "C" void kernel_launch(void* const* d_in, const int* in_sizes, int n_in,
                              void* d_out, int out_size) {
    const float* z   = (const float*)d_in[0];   // (16, 128, 64, 64)
    const float* emb = (const float*)d_in[1];   // (1024, 128)
    float* out = (float*)d_out;

    cudaFuncSetAttribute(vq_main_kernel,
                         cudaFuncAttributeMaxDynamicSharedMemorySize, SMEM_BYTES);

    prep_kernel<<<128, 256>>>(emb);
    vq_main_kernel<<<NBLOCKS, 256, SMEM_BYTES>>>(z, emb, out);
}

// round 8
// speedup vs baseline: 2.0903x; 1.3185x over previous
#include <cuda_runtime.h>
#include <cstdint>

#define NUM_E   1024
#define DIM     128
#define HW      4096
#define NBLOCKS 512           // 65536 rows / 128 per CTA

// Output layout (flattened tuple, float32)
#define OFF_LOSS   8388608
#define OFF_IDX    8388609
#define OFF_COMMIT 8454145
#define OFF_CODE   8454146

#define MARGIN 1.2e-4f

__device__ float    d_enorm[NUM_E];
__device__ float    d_blockS[NBLOCKS];
__device__ __align__(16) uint32_t d_bfrag[16 * 64 * 32 * 4]; // [kg][nblk][lane][slot]
__device__ unsigned d_ctr = 0;

// SMEM (byte offsets)
#define SM_AHI  0          // A-hi frag layout, 64KB
#define SM_Z    65536      // z plain [d][n] f32, 64KB
#define SM_E2   131072     // 1024 f32
#define SM_Z2   135168     // 128 f32
#define SM_CAND 135680     // 128 rows x 16 u64 = 16KB
#define SM_IDX  152064     // 128 i32
#define SM_WSUM 152576     // 8 f32
#define SM_FLAG 152608
#define SMEM_BYTES 152640

static __device__ __forceinline__ uint32_t cvt_tf32(float x) {
    uint32_t b;
    asm("cvt.rna.tf32.f32 %0, %1;" : "=r"(b) : "f"(x));
    return b;
}
static __device__ __forceinline__ void mma8(float c[4], const uint32_t a[4],
                                            uint32_t b0, uint32_t b1) {
    asm("mma.sync.aligned.m16n8k8.row.col.f32.tf32.tf32.f32 "
        "{%0,%1,%2,%3}, {%4,%5,%6,%7}, {%8,%9}, {%0,%1,%2,%3};"
        : "+f"(c[0]), "+f"(c[1]), "+f"(c[2]), "+f"(c[3])
        : "r"(a[0]), "r"(a[1]), "r"(a[2]), "r"(a[3]), "r"(b0), "r"(b1));
}
// element (m 0..127, k 0..127) -> byte offset in A frag layout
static __device__ __forceinline__ int afrag_off(int m, int k) {
    int lane = ((m & 7) << 2) | (k & 3);
    int slot = ((m >> 3) & 1) | (((k >> 2) & 1) << 1);
    return ((((k >> 3) << 3) + (m >> 4)) << 9) + (lane << 4) + (slot << 2);
}

// ---------------------------------------------------------------------------
// Prep: ||e||^2 + tf32-hi codebook written directly in B-fragment order.
// 128 blocks x 256 threads, one warp per code.
// ---------------------------------------------------------------------------
__global__ void prep_kernel(const float* __restrict__ emb) {
    int k    = blockIdx.x * 8 + (threadIdx.x >> 5);   // code id
    int lane = threadIdx.x & 31;
    const float4* row = (const float4*)(emb + (size_t)k * DIM);
    float4 v = row[lane];
    float s = __fadd_rn(__fadd_rn(__fmul_rn(v.x, v.x), __fmul_rn(v.y, v.y)),
                        __fadd_rn(__fmul_rn(v.z, v.z), __fmul_rn(v.w, v.w)));
    #pragma unroll
    for (int o = 16; o; o >>= 1) s = __fadd_rn(s, __shfl_xor_sync(0xffffffffu, s, o));
    if (lane == 0) d_enorm[k] = s;

    int nblk = k >> 4, nn = k & 15;
    float xv[4] = {v.x, v.y, v.z, v.w};
    #pragma unroll
    for (int e = 0; e < 4; e++) {
        int kk = lane * 4 + e;
        uint32_t hb = cvt_tf32(xv[e]);
        int kg   = kk >> 3;
        int fl   = ((nn & 7) << 2) | (kk & 3);
        int slot = ((kk >> 2) & 1) | (((nn >> 3) & 1) << 1);
        d_bfrag[(((kg << 6) + nblk) << 7) + (fl << 2) + slot] = hb;
    }
}

// ---------------------------------------------------------------------------
// Main: 512 CTAs x 256 threads. warp_m = wid>>1 (4 x M32), warp_n = wid&1
// (2 x N64). Per warp: 2 m-frags x 8 n-frags of m16n8k8. No barriers in
// the mainloop: A frags read-only in SMEM, B frags streamed from global.
// ---------------------------------------------------------------------------
__global__ __launch_bounds__(256, 1)
void vq_main_kernel(const float* __restrict__ z,
                    const float* __restrict__ emb,
                    float* __restrict__ out) {
    extern __shared__ char smem[];
    float* zpl  = (float*)(smem + SM_Z);      // zpl[d*128+n]
    float* e2sm = (float*)(smem + SM_E2);
    float* z2sm = (float*)(smem + SM_Z2);
    int*   idxsm = (int*)(smem + SM_IDX);
    float* wsum  = (float*)(smem + SM_WSUM);
    unsigned long long* cand = (unsigned long long*)(smem + SM_CAND);

    const int t    = threadIdx.x;
    const int wid  = t >> 5;
    const int lane = t & 31;
    const int warp_m = wid >> 1;              // 0..3
    const int warp_n = wid & 1;               // 0..1
    const int blk = blockIdx.x;
    const int n0  = blk * 128;
    const int b   = n0 >> 12;
    const int hw0 = n0 & 4095;
    const float* zbase = z + (size_t)b * (DIM * HW) + hw0;

    // e2 table
    #pragma unroll
    for (int i = 0; i < 4; i++) e2sm[i * 256 + t] = d_enorm[i * 256 + t];

    // ---- load z tile into zpl[d][n] (coalesced float4) ----
    #pragma unroll
    for (int i = 0; i < 16; i++) {
        int id = t + 256 * i;
        int dl = id >> 5, hw4 = (id & 31) * 4;
        float4 v = *(const float4*)(zbase + (size_t)dl * HW + hw4);
        *(float4*)(&zpl[dl * 128 + hw4]) = v;
    }
    __syncthreads();

    // ---- A-hi frags + strictly sequential z2 per row ----
    if (t < 128) {
        float z2 = 0.f;
        #pragma unroll 4
        for (int d = 0; d < 128; d++) {
            float v = zpl[d * 128 + t];
            z2 = __fadd_rn(z2, __fmul_rn(v, v));
            *(uint32_t*)(smem + SM_AHI + afrag_off(t, d)) = cvt_tf32(v);
        }
        z2sm[t] = z2;
    }
    __syncthreads();

    float z2r[4];                              // slots (mf,h)
    #pragma unroll
    for (int mf = 0; mf < 2; mf++)
        #pragma unroll
        for (int h = 0; h < 2; h++)
            z2r[mf * 2 + h] = z2sm[warp_m * 32 + mf * 16 + h * 8 + (lane >> 2)];

    unsigned long long best0[4], best1[4];
    #pragma unroll
    for (int i = 0; i < 4; i++) { best0[i] = ~0ull; best1[i] = ~0ull; }

    const uint4* bglob = (const uint4*)d_bfrag;

    #pragma unroll 1
    for (int j = 0; j < 8; j++) {              // n-tiles of 128 codes
        float acc[2][8][4];
        #pragma unroll
        for (int mf = 0; mf < 2; mf++)
            #pragma unroll
            for (int nf = 0; nf < 8; nf++)
                #pragma unroll
                for (int q = 0; q < 4; q++) acc[mf][nf][q] = 0.f;

        // B ring (depth 3) + A double buffer
        uint4 bf[4][4];
        uint4 af[2][2];
        #pragma unroll
        for (int kg = 0; kg < 3; kg++)
            #pragma unroll
            for (int i = 0; i < 4; i++)
                bf[kg][i] = bglob[((kg << 6) + (j << 3) + (warp_n << 2) + i) * 32 + lane];
        #pragma unroll
        for (int mf = 0; mf < 2; mf++)
            af[0][mf] = *(const uint4*)(smem + SM_AHI
                      + (((warp_m << 1) + mf) << 9) + (lane << 4));

        #pragma unroll
        for (int kg = 0; kg < 16; kg++) {
            if (kg + 3 < 16) {
                #pragma unroll
                for (int i = 0; i < 4; i++)
                    bf[(kg + 3) & 3][i] = bglob[(((kg + 3) << 6) + (j << 3)
                                          + (warp_n << 2) + i) * 32 + lane];
            }
            if (kg + 1 < 16) {
                #pragma unroll
                for (int mf = 0; mf < 2; mf++)
                    af[(kg + 1) & 1][mf] = *(const uint4*)(smem + SM_AHI
                        + ((((kg + 1) << 3) + (warp_m << 1) + mf) << 9) + (lane << 4));
            }
            const uint4* bc = bf[kg & 3];
            #pragma unroll
            for (int mf = 0; mf < 2; mf++) {
                const uint32_t* av = (const uint32_t*)&af[kg & 1][mf];
                #pragma unroll
                for (int i = 0; i < 4; i++) {
                    mma8(acc[mf][i * 2 + 0], av, bc[i].x, bc[i].y);
                    mma8(acc[mf][i * 2 + 1], av, bc[i].z, bc[i].w);
                }
            }
        }

        // approx scoring + per-slot top-2
        float e2v[8][2];
        int   ncb[8];
        #pragma unroll
        for (int nf = 0; nf < 8; nf++) {
            ncb[nf] = j * 128 + warp_n * 64 + nf * 8 + ((lane & 3) << 1);
            e2v[nf][0] = e2sm[ncb[nf]];
            e2v[nf][1] = e2sm[ncb[nf] + 1];
        }
        #pragma unroll
        for (int mf = 0; mf < 2; mf++)
            #pragma unroll
            for (int nf = 0; nf < 8; nf++)
                #pragma unroll
                for (int h = 0; h < 2; h++)
                    #pragma unroll
                    for (int q = 0; q < 2; q++) {
                        float dot = acc[mf][nf][h * 2 + q];
                        float s = __fadd_rn(__fadd_rn(z2r[mf * 2 + h], e2v[nf][q]),
                                            __fmul_rn(-2.0f, dot));
                        unsigned long long u =
                            ((unsigned long long)__float_as_uint(s) << 32)
                            | (unsigned)(ncb[nf] + q);
                        int sl = mf * 2 + h;
                        if (u < best0[sl]) { best1[sl] = best0[sl]; best0[sl] = u; }
                        else if (u < best1[sl]) { best1[sl] = u; }
                    }
    }

    // ---- dump candidates: cand[m][16] ----
    __syncthreads();
    {
        int ci = warp_n * 4 + (lane & 3);      // 0..7
        #pragma unroll
        for (int mf = 0; mf < 2; mf++)
            #pragma unroll
            for (int h = 0; h < 2; h++) {
                int m = warp_m * 32 + mf * 16 + h * 8 + (lane >> 2);
                cand[m * 16 + ci * 2 + 0] = best0[mf * 2 + h];
                cand[m * 16 + ci * 2 + 1] = best1[mf * 2 + h];
            }
    }
    __syncthreads();

    // ---- per-row: merge, margin-select, EXACT refine ----
    if (t < 128) {
        unsigned long long m0 = ~0ull;
        #pragma unroll
        for (int ci = 0; ci < 16; ci++) {
            unsigned long long u = cand[t * 16 + ci];
            if (u < m0) m0 = u;
        }
        float thr = __uint_as_float((uint32_t)(m0 >> 32)) + MARGIN;
        int cl[6]; int nc = 0;
        #pragma unroll
        for (int ci = 0; ci < 16; ci++) {
            unsigned long long u = cand[t * 16 + ci];
            float sv = __uint_as_float((uint32_t)(u >> 32));
            if (sv <= thr && nc < 6) cl[nc++] = (int)(u & 0xffffffffu);
        }
        float z2 = z2sm[t];
        unsigned long long bestu = ~0ull;
        for (int i = 0; i < nc; i++) {
            int k = cl[i];
            const float4* er = (const float4*)(emb + (size_t)k * DIM);
            float a0 = 0.f, a1 = 0.f, a2 = 0.f, a3 = 0.f;
            #pragma unroll 8
            for (int q = 0; q < 32; q++) {
                float4 e4 = er[q];
                int d0 = q * 4;
                a0 = fmaf(zpl[(d0 + 0) * 128 + t], e4.x, a0);
                a1 = fmaf(zpl[(d0 + 1) * 128 + t], e4.y, a1);
                a2 = fmaf(zpl[(d0 + 2) * 128 + t], e4.z, a2);
                a3 = fmaf(zpl[(d0 + 3) * 128 + t], e4.w, a3);
            }
            float dot = __fadd_rn(__fadd_rn(a0, a1), __fadd_rn(a2, a3));
            float s = __fadd_rn(__fadd_rn(z2, e2sm[k]), __fmul_rn(-2.0f, dot));
            unsigned long long u =
                ((unsigned long long)__float_as_uint(s) << 32) | (unsigned)k;
            if (u < bestu) bestu = u;
        }
        int idx = (int)(bestu & 0xffffffffu);
        idxsm[t] = idx;
        out[OFF_IDX + n0 + t] = (float)idx;
    }
    __syncthreads();

    // ---- epilogue: z_q gather+write, loss partial ----
    float sloc = 0.f;
    #pragma unroll 4
    for (int r = 0; r < 64; r++) {
        int linear = t + (r << 8);
        int d = linear >> 7;
        int n = linear & 127;
        float v  = emb[(size_t)idxsm[n] * DIM + d];
        float zv = zpl[d * 128 + n];
        float diff = v - zv;
        sloc = fmaf(diff, diff, sloc);
        out[(size_t)b * (DIM * HW) + (size_t)d * HW + hw0 + n] = v;
    }
    #pragma unroll
    for (int o = 16; o; o >>= 1) sloc += __shfl_xor_sync(0xffffffffu, sloc, o);
    if (lane == 0) wsum[wid] = sloc;
    __syncthreads();
    if (t == 0) {
        float s = 0.f;
        #pragma unroll
        for (int i = 0; i < 8; i++) s += wsum[i];
        d_blockS[blk] = s;
        __threadfence();
        unsigned v = atomicAdd(&d_ctr, 1u);
        *(unsigned*)(smem + SM_FLAG) = (v == (unsigned)(gridDim.x - 1));
    }
    __syncthreads();

    // ---- last block: deterministic finalize ----
    if (*(unsigned*)(smem + SM_FLAG)) {
        float* scratch = (float*)(smem + SM_CAND);
        scratch[t] = d_blockS[t] + d_blockS[t + 256];
        __syncthreads();
        for (int s = 128; s > 0; s >>= 1) {
            if (t < s) scratch[t] += scratch[t + s];
            __syncthreads();
        }
        if (t == 0) {
            float S = scratch[0];
            out[OFF_LOSS]   = 1.25f * S;
            out[OFF_COMMIT] = 0.25f * S;
            out[OFF_CODE]   = S;
            d_ctr = 0;                          // reset for next graph replay
        }
    }
}

// ---------------------------------------------------------------------------
extern "C" void kernel_launch(void* const* d_in, const int* in_sizes, int n_in,
                              void* d_out, int out_size) {
    const float* z   = (const float*)d_in[0];   // (16, 128, 64, 64)
    const float* emb = (const float*)d_in[1];   // (1024, 128)
    float* out = (float*)d_out;

    cudaFuncSetAttribute(vq_main_kernel,
                         cudaFuncAttributeMaxDynamicSharedMemorySize, SMEM_BYTES);

    prep_kernel<<<128, 256>>>(emb);
    vq_main_kernel<<<NBLOCKS, 256, SMEM_BYTES>>>(z, emb, out);
}

// round 9
// speedup vs baseline: 2.1707x; 1.0385x over previous
#include <cuda_runtime.h>
#include <cstdint>

#define NUM_E   1024
#define DIM     128
#define HW      4096
#define NBLOCKS 512           // 65536 rows / 128 per CTA

// Output layout (flattened tuple, float32)
#define OFF_LOSS   8388608
#define OFF_IDX    8388609
#define OFF_COMMIT 8454145
#define OFF_CODE   8454146

#define MARGIN 1.2e-4f

__device__ float    d_enorm[NUM_E];
__device__ float    d_blockS[NBLOCKS];
__device__ __align__(16) uint32_t d_bfrag[16 * 64 * 32 * 4]; // [kg][nblk][lane][slot]
__device__ unsigned d_ctr = 0;

// SMEM (byte offsets)
#define SM_AHI  0          // A-hi frag layout, 64KB
#define SM_Z    65536      // z plain [d][n] f32, 64KB
#define SM_B    131072     // B staging: 2 x 32KB half-tile buffers
#define SM_E2   196608     // 1024 f32 (raw ||e||^2, for refine)
#define SM_E2C  200704     // 1024 f32 (1 + ||e||^2, for shortlist scoring)
#define SM_Z2   204800     // 128 f32
#define SM_IDX  205312     // 128 i32
#define SM_WSUM 205824     // 8 f32
#define SM_FLAG 205856
#define SMEM_BYTES 205888
// cand[128][16] u64 (16KB) aliases SM_B after the mainloop

static __device__ __forceinline__ uint32_t smem_u32(const void* p) {
    uint32_t a;
    asm("{ .reg .u64 t; cvta.to.shared.u64 t, %1; cvt.u32.u64 %0, t; }"
        : "=r"(a) : "l"(p));
    return a;
}
static __device__ __forceinline__ uint32_t cvt_tf32(float x) {
    uint32_t b;
    asm("cvt.rna.tf32.f32 %0, %1;" : "=r"(b) : "f"(x));
    return b;
}
static __device__ __forceinline__ void mma8(float c[4], const uint32_t a[4],
                                            uint32_t b0, uint32_t b1) {
    asm("mma.sync.aligned.m16n8k8.row.col.f32.tf32.tf32.f32 "
        "{%0,%1,%2,%3}, {%4,%5,%6,%7}, {%8,%9}, {%0,%1,%2,%3};"
        : "+f"(c[0]), "+f"(c[1]), "+f"(c[2]), "+f"(c[3])
        : "r"(a[0]), "r"(a[1]), "r"(a[2]), "r"(a[3]), "r"(b0), "r"(b1));
}
static __device__ __forceinline__ void cp16(uint32_t dst, const void* src) {
    asm volatile("cp.async.cg.shared.global [%0], [%1], 16;"
                 :: "r"(dst), "l"(src) : "memory");
}
static __device__ __forceinline__ void cp_commit() {
    asm volatile("cp.async.commit_group;" ::: "memory");
}
static __device__ __forceinline__ void cp_wait1() {
    asm volatile("cp.async.wait_group 1;" ::: "memory");
}
// element (m 0..127, k 0..127) -> byte offset in A frag layout
static __device__ __forceinline__ int afrag_off(int m, int k) {
    int lane = ((m & 7) << 2) | (k & 3);
    int slot = ((m >> 3) & 1) | (((k >> 2) & 1) << 1);
    return ((((k >> 3) << 3) + (m >> 4)) << 9) + (lane << 4) + (slot << 2);
}

// ---------------------------------------------------------------------------
// Prep: ||e||^2 + tf32-hi codebook written directly in B-fragment order.
// ---------------------------------------------------------------------------
__global__ void prep_kernel(const float* __restrict__ emb) {
    int k    = blockIdx.x * 8 + (threadIdx.x >> 5);   // code id
    int lane = threadIdx.x & 31;
    const float4* row = (const float4*)(emb + (size_t)k * DIM);
    float4 v = row[lane];
    float s = __fadd_rn(__fadd_rn(__fmul_rn(v.x, v.x), __fmul_rn(v.y, v.y)),
                        __fadd_rn(__fmul_rn(v.z, v.z), __fmul_rn(v.w, v.w)));
    #pragma unroll
    for (int o = 16; o; o >>= 1) s = __fadd_rn(s, __shfl_xor_sync(0xffffffffu, s, o));
    if (lane == 0) d_enorm[k] = s;

    int nblk = k >> 4, nn = k & 15;
    float xv[4] = {v.x, v.y, v.z, v.w};
    #pragma unroll
    for (int e = 0; e < 4; e++) {
        int kk = lane * 4 + e;
        uint32_t hb = cvt_tf32(xv[e]);
        int kg   = kk >> 3;
        int fl   = ((nn & 7) << 2) | (kk & 3);
        int slot = ((kk >> 2) & 1) | (((nn >> 3) & 1) << 1);
        d_bfrag[(((kg << 6) + nblk) << 7) + (fl << 2) + slot] = hb;
    }
}

// ---------------------------------------------------------------------------
// Main: 512 CTAs x 256 threads. warp_m = wid>>1 (4 x M32), warp_n = wid&1
// (2 x N64). Per warp: 2 m-frags x 8 n-frags of m16n8k8.
// B streamed gmem -> SMEM by cp.async in 32KB half-j-tiles, double-buffered.
// ---------------------------------------------------------------------------
__global__ __launch_bounds__(256, 1)
void vq_main_kernel(const float* __restrict__ z,
                    const float* __restrict__ emb,
                    float* __restrict__ out) {
    extern __shared__ char smem[];
    const uint32_t sb = smem_u32(smem);
    float* zpl   = (float*)(smem + SM_Z);
    float* e2sm  = (float*)(smem + SM_E2);
    float* e2c   = (float*)(smem + SM_E2C);
    float* z2sm  = (float*)(smem + SM_Z2);
    int*   idxsm = (int*)(smem + SM_IDX);
    float* wsum  = (float*)(smem + SM_WSUM);

    const int t    = threadIdx.x;
    const int wid  = t >> 5;
    const int lane = t & 31;
    const int warp_m = wid >> 1;              // 0..3
    const int warp_n = wid & 1;               // 0..1
    const int blk = blockIdx.x;
    const int n0  = blk * 128;
    const int b   = n0 >> 12;
    const int hw0 = n0 & 4095;
    const float* zbase = z + (size_t)b * (DIM * HW) + hw0;
    const char*  bgb   = (const char*)d_bfrag;

    // issue cp.async for pipeline stages s=0 and s=1 immediately
    // stage s: j = s>>1, half = s&1; chunk kgl = o: 4KB contiguous.
    #pragma unroll
    for (int s = 0; s < 2; s++) {
        uint32_t dbase = sb + SM_B + (s & 1) * 32768 + t * 16;
        const char* sb0 = bgb + ((s & 1) * 8) * 32768 + (s >> 1) * 4096 + t * 16;
        #pragma unroll
        for (int o = 0; o < 8; o++)
            cp16(dbase + o * 4096, sb0 + o * 32768);
        cp_commit();
    }

    // e2 / e2c tables
    #pragma unroll
    for (int i = 0; i < 4; i++) {
        float e = d_enorm[i * 256 + t];
        e2sm[i * 256 + t] = e;
        e2c[i * 256 + t]  = 1.0f + e;
    }

    // ---- load z tile into zpl[d][n] (coalesced float4) ----
    #pragma unroll
    for (int i = 0; i < 16; i++) {
        int id = t + 256 * i;
        int dl = id >> 5, hw4 = (id & 31) * 4;
        float4 v = *(const float4*)(zbase + (size_t)dl * HW + hw4);
        *(float4*)(&zpl[dl * 128 + hw4]) = v;
    }
    __syncthreads();

    // ---- A-hi frags + strictly sequential z2 per row ----
    if (t < 128) {
        float z2 = 0.f;
        #pragma unroll 4
        for (int d = 0; d < 128; d++) {
            float v = zpl[d * 128 + t];
            z2 = __fadd_rn(z2, __fmul_rn(v, v));
            *(uint32_t*)(smem + SM_AHI + afrag_off(t, d)) = cvt_tf32(v);
        }
        z2sm[t] = z2;
    }

    unsigned long long best0[4], best1[4];
    #pragma unroll
    for (int i = 0; i < 4; i++) { best0[i] = ~0ull; best1[i] = ~0ull; }

    float acc[2][8][4];

    // ---- mainloop: 16 stages (8 j-tiles x 2 halves of 8 kg) ----
    #pragma unroll 1
    for (int s = 0; s < 16; s++) {
        const int j  = s >> 1;
        const int hf = s & 1;
        const uint32_t bbuf = sb + SM_B + (s & 1) * 32768;

        if (hf == 0) {
            #pragma unroll
            for (int mf = 0; mf < 2; mf++)
                #pragma unroll
                for (int nf = 0; nf < 8; nf++)
                    #pragma unroll
                    for (int q = 0; q < 4; q++) acc[mf][nf][q] = 0.f;
        }

        cp_wait1();                     // stage s data resident
        __syncthreads();                // visible to all warps; prior reads done

        // mma over 8 kg of this half-tile, reg double-buffered LDS
        {
            uint4 bf[2][4], af[2][2];
            #pragma unroll
            for (int i = 0; i < 4; i++)
                bf[0][i] = *(const uint4*)(smem + SM_B + (s & 1) * 32768
                          + ((warp_n << 2) + i) * 512 + lane * 16);
            #pragma unroll
            for (int mf = 0; mf < 2; mf++)
                af[0][mf] = *(const uint4*)(smem + SM_AHI
                          + ((((hf << 3) << 3) + (warp_m << 1) + mf) << 9) + (lane << 4));

            #pragma unroll
            for (int kgl = 0; kgl < 8; kgl++) {
                if (kgl + 1 < 8) {
                    #pragma unroll
                    for (int i = 0; i < 4; i++)
                        bf[(kgl + 1) & 1][i] = *(const uint4*)(smem + SM_B
                            + (s & 1) * 32768 + (kgl + 1) * 4096
                            + ((warp_n << 2) + i) * 512 + lane * 16);
                    int kgn = (hf << 3) + kgl + 1;
                    #pragma unroll
                    for (int mf = 0; mf < 2; mf++)
                        af[(kgl + 1) & 1][mf] = *(const uint4*)(smem + SM_AHI
                            + (((kgn << 3) + (warp_m << 1) + mf) << 9) + (lane << 4));
                }
                const uint4* bc = bf[kgl & 1];
                #pragma unroll
                for (int mf = 0; mf < 2; mf++) {
                    const uint32_t* av = (const uint32_t*)&af[kgl & 1][mf];
                    #pragma unroll
                    for (int i = 0; i < 4; i++) {
                        mma8(acc[mf][i * 2 + 0], av, bc[i].x, bc[i].y);
                        mma8(acc[mf][i * 2 + 1], av, bc[i].z, bc[i].w);
                    }
                }
            }
        }
        __syncthreads();                // all warps done reading buffer s&1

        if (s + 2 < 16) {               // prefetch stage s+2 into buffer s&1
            uint32_t dbase = sb + SM_B + (s & 1) * 32768 + t * 16;
            const char* sp = bgb + (((s + 2) & 1) * 8) * 32768
                           + ((s + 2) >> 1) * 4096 + t * 16;
            #pragma unroll
            for (int o = 0; o < 8; o++)
                cp16(dbase + o * 4096, sp + o * 32768);
            cp_commit();
        } else {
            cp_commit();                // keep wait_group(1) accounting uniform
        }

        if (hf == 1) {
            // shortlist scoring: s = fl((1+e2) - 2*dot); row-constant z2 dropped
            float e2v[8][2];
            int   ncb[8];
            #pragma unroll
            for (int nf = 0; nf < 8; nf++) {
                ncb[nf] = j * 128 + warp_n * 64 + nf * 8 + ((lane & 3) << 1);
                e2v[nf][0] = e2c[ncb[nf]];
                e2v[nf][1] = e2c[ncb[nf] + 1];
            }
            #pragma unroll
            for (int mf = 0; mf < 2; mf++)
                #pragma unroll
                for (int nf = 0; nf < 8; nf++)
                    #pragma unroll
                    for (int h = 0; h < 2; h++)
                        #pragma unroll
                        for (int q = 0; q < 2; q++) {
                            float sv = __fmaf_rn(-2.0f, acc[mf][nf][h * 2 + q],
                                                 e2v[nf][q]);
                            unsigned long long u =
                                ((unsigned long long)__float_as_uint(sv) << 32)
                                | (unsigned)(ncb[nf] + q);
                            int sl = mf * 2 + h;
                            if (u < best0[sl]) { best1[sl] = best0[sl]; best0[sl] = u; }
                            else if (u < best1[sl]) { best1[sl] = u; }
                        }
        }
    }

    // ---- dump candidates: cand[m][16] (aliases B buffers) ----
    __syncthreads();
    unsigned long long* cand = (unsigned long long*)(smem + SM_B);
    {
        int ci = warp_n * 4 + (lane & 3);
        #pragma unroll
        for (int mf = 0; mf < 2; mf++)
            #pragma unroll
            for (int h = 0; h < 2; h++) {
                int m = warp_m * 32 + mf * 16 + h * 8 + (lane >> 2);
                cand[m * 16 + ci * 2 + 0] = best0[mf * 2 + h];
                cand[m * 16 + ci * 2 + 1] = best1[mf * 2 + h];
            }
    }
    __syncthreads();

    // ---- per-row: merge, margin-select, EXACT refine ----
    if (t < 128) {
        unsigned long long m0 = ~0ull;
        #pragma unroll
        for (int ci = 0; ci < 16; ci++) {
            unsigned long long u = cand[t * 16 + ci];
            if (u < m0) m0 = u;
        }
        float thr = __uint_as_float((uint32_t)(m0 >> 32)) + MARGIN;
        int cl[6]; int nc = 0;
        #pragma unroll
        for (int ci = 0; ci < 16; ci++) {
            unsigned long long u = cand[t * 16 + ci];
            float sv = __uint_as_float((uint32_t)(u >> 32));
            if (sv <= thr && nc < 6) cl[nc++] = (int)(u & 0xffffffffu);
        }
        float z2 = z2sm[t];
        unsigned long long bestu = ~0ull;
        for (int i = 0; i < nc; i++) {
            int k = cl[i];
            const float4* er = (const float4*)(emb + (size_t)k * DIM);
            float a0 = 0.f, a1 = 0.f, a2 = 0.f, a3 = 0.f;
            #pragma unroll 8
            for (int q = 0; q < 32; q++) {
                float4 e4 = er[q];
                int d0 = q * 4;
                a0 = fmaf(zpl[(d0 + 0) * 128 + t], e4.x, a0);
                a1 = fmaf(zpl[(d0 + 1) * 128 + t], e4.y, a1);
                a2 = fmaf(zpl[(d0 + 2) * 128 + t], e4.z, a2);
                a3 = fmaf(zpl[(d0 + 3) * 128 + t], e4.w, a3);
            }
            float dot = __fadd_rn(__fadd_rn(a0, a1), __fadd_rn(a2, a3));
            float s = __fadd_rn(__fadd_rn(z2, e2sm[k]), __fmul_rn(-2.0f, dot));
            unsigned long long u =
                ((unsigned long long)__float_as_uint(s) << 32) | (unsigned)k;
            if (u < bestu) bestu = u;
        }
        int idx = (int)(bestu & 0xffffffffu);
        idxsm[t] = idx;
        out[OFF_IDX + n0 + t] = (float)idx;
    }
    __syncthreads();

    // ---- epilogue: z_q gather+write, loss partial ----
    float sloc = 0.f;
    #pragma unroll 4
    for (int r = 0; r < 64; r++) {
        int linear = t + (r << 8);
        int d = linear >> 7;
        int n = linear & 127;
        float v  = emb[(size_t)idxsm[n] * DIM + d];
        float zv = zpl[d * 128 + n];
        float diff = v - zv;
        sloc = fmaf(diff, diff, sloc);
        out[(size_t)b * (DIM * HW) + (size_t)d * HW + hw0 + n] = v;
    }
    #pragma unroll
    for (int o = 16; o; o >>= 1) sloc += __shfl_xor_sync(0xffffffffu, sloc, o);
    if (lane == 0) wsum[wid] = sloc;
    __syncthreads();
    if (t == 0) {
        float s = 0.f;
        #pragma unroll
        for (int i = 0; i < 8; i++) s += wsum[i];
        d_blockS[blk] = s;
        __threadfence();
        unsigned v = atomicAdd(&d_ctr, 1u);
        *(unsigned*)(smem + SM_FLAG) = (v == (unsigned)(gridDim.x - 1));
    }
    __syncthreads();

    // ---- last block: deterministic finalize ----
    if (*(unsigned*)(smem + SM_FLAG)) {
        float* scratch = (float*)(smem + SM_B);
        scratch[t] = d_blockS[t] + d_blockS[t + 256];
        __syncthreads();
        for (int s = 128; s > 0; s >>= 1) {
            if (t < s) scratch[t] += scratch[t + s];
            __syncthreads();
        }
        if (t == 0) {
            float S = scratch[0];
            out[OFF_LOSS]   = 1.25f * S;
            out[OFF_COMMIT] = 0.25f * S;
            out[OFF_CODE]   = S;
            d_ctr = 0;                          // reset for next graph replay
        }
    }
}

// ---------------------------------------------------------------------------
extern "C" void kernel_launch(void* const* d_in, const int* in_sizes, int n_in,
                              void* d_out, int out_size) {
    const float* z   = (const float*)d_in[0];   // (16, 128, 64, 64)
    const float* emb = (const float*)d_in[1];   // (1024, 128)
    float* out = (float*)d_out;

    cudaFuncSetAttribute(vq_main_kernel,
                         cudaFuncAttributeMaxDynamicSharedMemorySize, SMEM_BYTES);

    prep_kernel<<<128, 256>>>(emb);
    vq_main_kernel<<<NBLOCKS, 256, SMEM_BYTES>>>(z, emb, out);
}